// round 4
// baseline (speedup 1.0000x reference)
#include <cuda_runtime.h>
#include <math.h>

#define B_ 2048
#define T_ 200
#define C_ 128
#define THREADS 256
#define NW 8

typedef unsigned long long u64;

__device__ __forceinline__ u64 fma2(u64 a, u64 b, u64 c) {
    u64 d; asm("fma.rn.f32x2 %0, %1, %2, %3;" : "=l"(d) : "l"(a), "l"(b), "l"(c));
    return d;
}
__device__ __forceinline__ u64 mul2(u64 a, u64 b) {
    u64 d; asm("mul.rn.f32x2 %0, %1, %2;" : "=l"(d) : "l"(a), "l"(b));
    return d;
}
__device__ __forceinline__ u64 add2(u64 a, u64 b) {
    u64 d; asm("add.rn.f32x2 %0, %1, %2;" : "=l"(d) : "l"(a), "l"(b));
    return d;
}
__device__ __forceinline__ float lohisum(u64 a) {
    float lo, hi; asm("mov.b64 {%0,%1}, %2;" : "=f"(lo), "=f"(hi) : "l"(a));
    return lo + hi;
}
__device__ __forceinline__ u64 dup2(float x) {
    u64 d; asm("mov.b64 %0, {%1,%1};" : "=l"(d) : "f"(x));
    return d;
}

__global__ void __launch_bounds__(THREADS)
fused_kernel(const float* __restrict__ uq,
             const float* __restrict__ keys,
             const int*   __restrict__ keys_length,
             const float* __restrict__ W,
             const float* __restrict__ bias,
             float*       __restrict__ out) {
    __shared__ float suq[C_];
    __shared__ float spart[2][C_];
    __shared__ float sq[C_];
    __shared__ float sm_s[16];
    __shared__ ulonglong2 sA[NW][32], sB[NW][32], sKA[NW][32], sKB[NW][32];

    const int tid  = threadIdx.x;
    const int b    = blockIdx.x;
    const int lane = tid & 31;
    const int w    = tid >> 5;
    const int l16  = lane & 15;
    const int g    = lane >> 4;

    // ---- phase 0: q = tanh(uq[b] @ W + bias) * scale ----
    if (tid < 32)
        ((float4*)suq)[tid] = ((const float4*)(uq + (size_t)b * C_))[tid];
    __syncthreads();
    {
        const int c = tid & (C_ - 1);
        const int h = tid >> 7;
        const float* Wp = W + (size_t)(h * 64) * C_ + c;
        const float* u  = suq + h * 64;
        float a0 = 0.f, a1 = 0.f, a2 = 0.f, a3 = 0.f;
        #pragma unroll 16
        for (int d = 0; d < 64; d += 4) {
            a0 = fmaf(u[d + 0], Wp[(d + 0) * C_], a0);
            a1 = fmaf(u[d + 1], Wp[(d + 1) * C_], a1);
            a2 = fmaf(u[d + 2], Wp[(d + 2) * C_], a2);
            a3 = fmaf(u[d + 3], Wp[(d + 3) * C_], a3);
        }
        spart[h][c] = (a0 + a1) + (a2 + a3);
    }
    __syncthreads();
    if (tid < C_)
        sq[tid] = tanhf(spart[0][tid] + spart[1][tid] + bias[tid])
                  * 0.08838834764831845f;   // fold 1/sqrt(128)
    __syncthreads();

    // ---- phase 1: streaming softmax-weighted sum (16-lane groups) ----
    const int len = keys_length[b];
    const ulonglong2* gku = (const ulonglong2*)(keys + (size_t)b * T_ * C_);
    const ulonglong2  qA  = ((const ulonglong2*)sq)[l16];
    const ulonglong2  qB  = ((const ulonglong2*)sq)[16 + l16];

    u64 aA0 = 0, aA1 = 0, aB0 = 0, aB1 = 0;      // weighted acc (packed)
    u64 kA0 = 0, kA1 = 0, kB0 = 0, kB1 = 0;      // plain key sums (packed)
    float s = 0.f;

#define ROUND(T)                                                              \
    {                                                                         \
        const int t_ = (T);                                                   \
        const ulonglong2 ka = gku[t_ * 32 + l16];                             \
        const ulonglong2 kb = gku[t_ * 32 + 16 + l16];                        \
        u64 d2 = fma2(qA.x, ka.x,                                             \
                 fma2(qA.y, ka.y,                                             \
                 fma2(qB.x, kb.x, mul2(qB.y, kb.y))));                        \
        float d = lohisum(d2);                                                \
        d += __shfl_xor_sync(0xffffffffu, d, 8);                              \
        d += __shfl_xor_sync(0xffffffffu, d, 4);                              \
        d += __shfl_xor_sync(0xffffffffu, d, 2);                              \
        d += __shfl_xor_sync(0xffffffffu, d, 1);                              \
        const float e = (t_ < len) ? __expf(d) : 0.f;                         \
        s += e;                                                               \
        const u64 e2 = dup2(e);                                               \
        aA0 = fma2(e2, ka.x, aA0); aA1 = fma2(e2, ka.y, aA1);                 \
        aB0 = fma2(e2, kb.x, aB0); aB1 = fma2(e2, kb.y, aB1);                 \
        kA0 = add2(kA0, ka.x); kA1 = add2(kA1, ka.y);                         \
        kB0 = add2(kB0, kb.x); kB1 = add2(kB1, kb.y);                         \
    }

    #pragma unroll 4
    for (int r = 0; r < 12; r++)
        ROUND(r * 16 + w * 2 + g);
    if (w < 4)                                   // tail t = 192..199
        ROUND(192 + w * 2 + g);
#undef ROUND

    if (l16 == 0) sm_s[w * 2 + g] = s;
    sA [w][lane] = make_ulonglong2(aA0, aA1);
    sB [w][lane] = make_ulonglong2(aB0, aB1);
    sKA[w][lane] = make_ulonglong2(kA0, kA1);
    sKB[w][lane] = make_ulonglong2(kB0, kB1);
    __syncthreads();

    // ---- epilogue: 1 warp combines 16 partials per channel chunk ----
    if (tid < 32) {
        float S = 0.f;
        #pragma unroll
        for (int j = 0; j < 16; j++) S += sm_s[j];

        const int c = tid;
        const float4* pA  = (const float4*)sA;
        const float4* pB  = (const float4*)sB;
        const float4* pKA = (const float4*)sKA;
        const float4* pKB = (const float4*)sKB;

        float4 r = make_float4(0.f, 0.f, 0.f, 0.f);
        float4 k = make_float4(0.f, 0.f, 0.f, 0.f);
        if (c < 16) {
            #pragma unroll
            for (int j = 0; j < NW; j++) {
                const float4 x0 = pA [j * 32 + c], x1 = pA [j * 32 + c + 16];
                const float4 y0 = pKA[j * 32 + c], y1 = pKA[j * 32 + c + 16];
                r.x += x0.x + x1.x; r.y += x0.y + x1.y;
                r.z += x0.z + x1.z; r.w += x0.w + x1.w;
                k.x += y0.x + y1.x; k.y += y0.y + y1.y;
                k.z += y0.z + y1.z; k.w += y0.w + y1.w;
            }
        } else {
            #pragma unroll
            for (int j = 0; j < NW; j++) {
                const float4 x0 = pB [j * 32 + c - 16], x1 = pB [j * 32 + c];
                const float4 y0 = pKB[j * 32 + c - 16], y1 = pKB[j * 32 + c];
                r.x += x0.x + x1.x; r.y += x0.y + x1.y;
                r.z += x0.z + x1.z; r.w += x0.w + x1.w;
                k.x += y0.x + y1.x; k.y += y0.y + y1.y;
                k.z += y0.z + y1.z; k.w += y0.w + y1.w;
            }
        }

        const float invT = 1.0f / (float)T_;
        float4 o;
        if (S > 0.f) {
            const float invS = 1.0f / S;
            o.x = fmaf(r.x, invS, k.x * invT);
            o.y = fmaf(r.y, invS, k.y * invT);
            o.z = fmaf(r.z, invS, k.z * invT);
            o.w = fmaf(r.w, invS, k.w * invT);
        } else {                                 // len==0: uniform softmax
            const float u2 = 2.0f * invT;
            o.x = k.x * u2; o.y = k.y * u2; o.z = k.z * u2; o.w = k.w * u2;
        }
        ((float4*)(out + (size_t)b * C_))[c] = o;
    }
}

// ---------------------------------------------------------------------------
extern "C" void kernel_launch(void* const* d_in, const int* in_sizes, int n_in,
                              void* d_out, int out_size) {
    const float* uq   = (const float*)d_in[0];   // [B,1,C]
    const float* keys = (const float*)d_in[1];   // [B,T,C]
    const int*   klen = (const int*)d_in[2];     // [B,1]
    const float* W    = (const float*)d_in[3];   // [C,C]
    const float* bias = (const float*)d_in[4];   // [C]
    float* out = (float*)d_out;                  // [B,1,C]

    fused_kernel<<<B_, THREADS>>>(uq, keys, klen, W, bias, out);
}

// round 5
// speedup vs baseline: 1.2295x; 1.2295x over previous
#include <cuda_runtime.h>
#include <math.h>

#define B_ 2048
#define T_ 200
#define C_ 128
#define THREADS 256
#define NW 8
#define CT 40                    // timesteps per chunk
#define NCH 5                    // 200 / 40
#define F4_PER_CHUNK (CT * 32)   // 1280 float4
#define F4_PER_THREAD (F4_PER_CHUNK / THREADS)  // 5

__device__ __forceinline__ void cp16(float4* dst, const float4* src) {
    unsigned int s = (unsigned int)__cvta_generic_to_shared(dst);
    asm volatile("cp.async.cg.shared.global [%0], [%1], 16;\n" :: "r"(s), "l"(src));
}

__global__ void __launch_bounds__(THREADS)
fused_kernel(const float* __restrict__ uq,
             const float* __restrict__ keys,
             const int*   __restrict__ keys_length,
             const float* __restrict__ W,
             const float* __restrict__ bias,
             float*       __restrict__ out) {
    __shared__ float4 sbuf[2][F4_PER_CHUNK];     // 40 KB double buffer
    __shared__ float  suq[C_];
    __shared__ float  spart[2][C_];
    __shared__ float  sq[C_];
    __shared__ float  sm_s[NW];
    __shared__ float4 sm_acc[NW * 32];
    __shared__ float4 sm_ksum[NW * 32];

    const int tid  = threadIdx.x;
    const int b    = blockIdx.x;
    const int lane = tid & 31;
    const int w    = tid >> 5;

    const float4* gk = (const float4*)(keys + (size_t)b * T_ * C_);

    // ---- prefetch chunks 0 and 1 immediately (overlaps with phase 0) ----
    #pragma unroll
    for (int i = 0; i < F4_PER_THREAD; i++)
        cp16(&sbuf[0][tid + i * THREADS], gk + tid + i * THREADS);
    asm volatile("cp.async.commit_group;\n" ::: "memory");
    #pragma unroll
    for (int i = 0; i < F4_PER_THREAD; i++)
        cp16(&sbuf[1][tid + i * THREADS], gk + F4_PER_CHUNK + tid + i * THREADS);
    asm volatile("cp.async.commit_group;\n" ::: "memory");

    // ---- phase 0: q = tanh(uq[b] @ W + bias) * 1/sqrt(C) ----
    if (tid < 32)
        ((float4*)suq)[tid] = ((const float4*)(uq + (size_t)b * C_))[tid];
    const int len = keys_length[b];
    __syncthreads();
    {
        const int c = tid & (C_ - 1);
        const int h = tid >> 7;
        const float* Wp = W + (size_t)(h * 64) * C_ + c;
        const float* u  = suq + h * 64;
        float a0 = 0.f, a1 = 0.f, a2 = 0.f, a3 = 0.f;
        #pragma unroll 16
        for (int d = 0; d < 64; d += 4) {
            a0 = fmaf(u[d + 0], Wp[(d + 0) * C_], a0);
            a1 = fmaf(u[d + 1], Wp[(d + 1) * C_], a1);
            a2 = fmaf(u[d + 2], Wp[(d + 2) * C_], a2);
            a3 = fmaf(u[d + 3], Wp[(d + 3) * C_], a3);
        }
        spart[h][c] = (a0 + a1) + (a2 + a3);
    }
    __syncthreads();
    if (tid < C_)
        sq[tid] = tanhf(spart[0][tid] + spart[1][tid] + bias[tid])
                  * 0.08838834764831845f;        // fold 1/sqrt(128)
    __syncthreads();

    const float4 q4 = ((const float4*)sq)[lane];

    float  s = 0.f;
    float4 acc  = make_float4(0.f, 0.f, 0.f, 0.f);
    float4 ksum = make_float4(0.f, 0.f, 0.f, 0.f);

    // ---- phase 1: chunked pipeline over keys ----
    #pragma unroll
    for (int c = 0; c < NCH; c++) {
        asm volatile("cp.async.wait_group 1;\n" ::: "memory");
        __syncthreads();

        const float4* buf = sbuf[c & 1];
        #pragma unroll
        for (int i = 0; i < CT / NW; i++) {      // 5 timesteps per warp
            const int tl = w + i * NW;
            const int t  = c * CT + tl;
            const float4 k4 = buf[tl * 32 + lane];

            float d = q4.x * k4.x + q4.y * k4.y + q4.z * k4.z + q4.w * k4.w;
            d += __shfl_xor_sync(0xffffffffu, d, 16);
            d += __shfl_xor_sync(0xffffffffu, d, 8);
            d += __shfl_xor_sync(0xffffffffu, d, 4);
            d += __shfl_xor_sync(0xffffffffu, d, 2);
            d += __shfl_xor_sync(0xffffffffu, d, 1);

            const float e = (t < len) ? __expf(d) : 0.f;
            s += e;
            acc.x = fmaf(e, k4.x, acc.x); acc.y = fmaf(e, k4.y, acc.y);
            acc.z = fmaf(e, k4.z, acc.z); acc.w = fmaf(e, k4.w, acc.w);
            ksum.x += k4.x; ksum.y += k4.y; ksum.z += k4.z; ksum.w += k4.w;
        }
        __syncthreads();

        if (c + 2 < NCH) {
            const float4* src = gk + (c + 2) * F4_PER_CHUNK;
            float4* dst = (float4*)sbuf[c & 1];
            #pragma unroll
            for (int i = 0; i < F4_PER_THREAD; i++)
                cp16(&dst[tid + i * THREADS], src + tid + i * THREADS);
        }
        asm volatile("cp.async.commit_group;\n" ::: "memory");
    }

    // ---- combine 8 warps ----
    if (lane == 0) sm_s[w] = s;
    sm_acc [w * 32 + lane] = acc;
    sm_ksum[w * 32 + lane] = ksum;
    __syncthreads();

    if (tid < 32) {
        float S = 0.f;
        float4 r = make_float4(0.f, 0.f, 0.f, 0.f);
        float4 k = make_float4(0.f, 0.f, 0.f, 0.f);
        #pragma unroll
        for (int j = 0; j < NW; j++) {
            S += sm_s[j];
            const float4 a  = sm_acc [j * 32 + tid];
            const float4 ks = sm_ksum[j * 32 + tid];
            r.x += a.x; r.y += a.y; r.z += a.z; r.w += a.w;
            k.x += ks.x; k.y += ks.y; k.z += ks.z; k.w += ks.w;
        }
        const float invT = 1.0f / (float)T_;
        float4 o;
        if (S > 0.f) {
            const float invS = 1.0f / S;
            o.x = fmaf(r.x, invS, k.x * invT);
            o.y = fmaf(r.y, invS, k.y * invT);
            o.z = fmaf(r.z, invS, k.z * invT);
            o.w = fmaf(r.w, invS, k.w * invT);
        } else {                                 // len==0: uniform softmax
            const float u2 = 2.0f * invT;
            o.x = k.x * u2; o.y = k.y * u2; o.z = k.z * u2; o.w = k.w * u2;
        }
        ((float4*)(out + (size_t)b * C_))[tid] = o;
    }
}

// ---------------------------------------------------------------------------
extern "C" void kernel_launch(void* const* d_in, const int* in_sizes, int n_in,
                              void* d_out, int out_size) {
    const float* uq   = (const float*)d_in[0];   // [B,1,C]
    const float* keys = (const float*)d_in[1];   // [B,T,C]
    const int*   klen = (const int*)d_in[2];     // [B,1]
    const float* W    = (const float*)d_in[3];   // [C,C]
    const float* bias = (const float*)d_in[4];   // [C]
    float* out = (float*)d_out;                  // [B,1,C]

    fused_kernel<<<B_, THREADS>>>(uq, keys, klen, W, bias, out);
}